// round 1
// baseline (speedup 1.0000x reference)
#include <cuda_runtime.h>
#include <math.h>

#define HD 512
#define BB 64
#define TK 512
#define NKN 256

// -------- scratch (device globals: no allocations allowed) --------
__device__ float g_dec[BB * HD];          // dec_fea [B,H]
__device__ float g_scores_tok[BB * TK];
__device__ float g_scores_node[BB * NKN];
__device__ float g_attn_node[BB * NKN];
__device__ float g_final[BB * TK];
__device__ float g_one_hop[BB * NKN];

__device__ __forceinline__ float fast_tanh(float x) {
    float y;
    asm("tanh.approx.f32 %0, %1;" : "=f"(y) : "f"(x));
    return y;
}

// ---------------- K0: zero scratch + c_t output region ----------------
__global__ void init_kernel(float* __restrict__ d_out) {
    int i = blockIdx.x * blockDim.x + threadIdx.x;
    if (i < BB * TK) {
        g_scores_tok[i] = 0.f;
    } else if (i < BB * TK + BB * NKN) {
        g_scores_node[i - BB * TK] = 0.f;
    } else {
        int j = i - (BB * TK + BB * NKN);
        if (j < BB * HD) d_out[j] = 0.f;   // c_t region (atomicAdd target)
    }
}

// ---------------- K1: dec_fea = s_t_hat @ W_dec + b_dec ----------------
__global__ void dec_kernel(const float* __restrict__ s_t,
                           const float* __restrict__ Wd,
                           const float* __restrict__ bd) {
    int b = blockIdx.x;
    int h = threadIdx.x;              // blockDim = 512
    __shared__ float ss[2 * HD];
    for (int k = h; k < 2 * HD; k += HD) ss[k] = s_t[b * 2 * HD + k];
    __syncthreads();
    float acc = bd[h];
    #pragma unroll 8
    for (int k = 0; k < 2 * HD; k++) acc = fmaf(ss[k], Wd[k * HD + h], acc);
    g_dec[b * HD + h] = acc;
}

// ---------------- K2: fused GEMM + tanh + v-dot (token / node) ----------------
// scores[m] += sum_n v[n] * tanh( (A@W)[m,n] + dec[b,n] (+ flow[m]*Wc[n]) )
template <int NODE>
__global__ void __launch_bounds__(256)
gemm_score(const float* __restrict__ A,   // [M, 512] row-major
           const float* __restrict__ W,   // [512, 512] row-major ([in,out])
           const float* __restrict__ flw, // [M] (node only)
           const float* __restrict__ Wc,  // [512] (node only)
           const float* __restrict__ v,   // [512]
           int rows_per_batch) {
    const int BM = 128, BN = 64, BK = 16;
    __shared__ float As[BK][BM];
    __shared__ float Bs[BK][BN];

    int tid = threadIdx.x;
    int tx = tid & 15;       // 0..15 -> 4 cols each
    int ty = tid >> 4;       // 0..15 -> 8 rows each
    int m0 = blockIdx.y * BM;
    int n0 = blockIdx.x * BN;

    float acc[8][4] = {};
    const float* Aptr = A + (size_t)m0 * HD;

    for (int k0 = 0; k0 < HD; k0 += BK) {
        // A tile: 128x16 = 512 float4 -> 2 per thread, stored transposed
        #pragma unroll
        for (int r = 0; r < 2; r++) {
            int idx = tid + r * 256;
            int row = idx >> 2, c4 = idx & 3;
            float4 va = *reinterpret_cast<const float4*>(Aptr + row * HD + k0 + c4 * 4);
            As[c4 * 4 + 0][row] = va.x;
            As[c4 * 4 + 1][row] = va.y;
            As[c4 * 4 + 2][row] = va.z;
            As[c4 * 4 + 3][row] = va.w;
        }
        // B tile: 16x64 = 256 float4 -> 1 per thread
        {
            int row = tid >> 4, c4 = tid & 15;
            *reinterpret_cast<float4*>(&Bs[row][c4 * 4]) =
                *reinterpret_cast<const float4*>(W + (k0 + row) * HD + n0 + c4 * 4);
        }
        __syncthreads();
        #pragma unroll
        for (int kk = 0; kk < BK; kk++) {
            float a[8];
            #pragma unroll
            for (int i = 0; i < 8; i++) a[i] = As[kk][ty * 8 + i];
            float4 b4 = *reinterpret_cast<float4*>(&Bs[kk][tx * 4]);
            float bf[4] = {b4.x, b4.y, b4.z, b4.w};
            #pragma unroll
            for (int i = 0; i < 8; i++)
                #pragma unroll
                for (int j = 0; j < 4; j++)
                    acc[i][j] = fmaf(a[i], bf[j], acc[i][j]);
        }
        __syncthreads();
    }

    // epilogue: tanh + dot with v, partial reduce over this block's 64 cols
    float* scores = NODE ? g_scores_node : g_scores_tok;
    int b = m0 / rows_per_batch;   // whole 128-row tile is within one batch
    float rs[8] = {};
    #pragma unroll
    for (int j = 0; j < 4; j++) {
        int n = n0 + tx * 4 + j;
        float d = g_dec[b * HD + n];
        float wc = NODE ? Wc[n] : 0.f;
        float vn = v[n];
        #pragma unroll
        for (int i = 0; i < 8; i++) {
            float val = acc[i][j] + d;
            if (NODE) val = fmaf(flw[m0 + ty * 8 + i], wc, val);
            rs[i] += vn * fast_tanh(val);
        }
    }
    // reduce across the 16 tx lanes (same 16-lane half-warp group)
    #pragma unroll
    for (int i = 0; i < 8; i++) {
        float s = rs[i];
        #pragma unroll
        for (int off = 8; off > 0; off >>= 1)
            s += __shfl_xor_sync(0xFFFFFFFFu, s, off, 16);
        if (tx == 0) atomicAdd(&scores[m0 + ty * 8 + i], s);
    }
}

// ---------------- block reduce helpers ----------------
__device__ __forceinline__ float blockReduceMax(float v, float* sh, int nwarp) {
    #pragma unroll
    for (int off = 16; off > 0; off >>= 1)
        v = fmaxf(v, __shfl_xor_sync(0xFFFFFFFFu, v, off));
    int lane = threadIdx.x & 31, w = threadIdx.x >> 5;
    if (lane == 0) sh[w] = v;
    __syncthreads();
    if (threadIdx.x < 32) {
        float x = (threadIdx.x < nwarp) ? sh[threadIdx.x] : -INFINITY;
        #pragma unroll
        for (int off = 16; off > 0; off >>= 1)
            x = fmaxf(x, __shfl_xor_sync(0xFFFFFFFFu, x, off));
        if (threadIdx.x == 0) sh[0] = x;
    }
    __syncthreads();
    float r = sh[0];
    __syncthreads();
    return r;
}

__device__ __forceinline__ float blockReduceSum(float v, float* sh, int nwarp) {
    #pragma unroll
    for (int off = 16; off > 0; off >>= 1)
        v += __shfl_xor_sync(0xFFFFFFFFu, v, off);
    int lane = threadIdx.x & 31, w = threadIdx.x >> 5;
    if (lane == 0) sh[w] = v;
    __syncthreads();
    if (threadIdx.x < 32) {
        float x = (threadIdx.x < nwarp) ? sh[threadIdx.x] : 0.f;
        #pragma unroll
        for (int off = 16; off > 0; off >>= 1)
            x += __shfl_xor_sync(0xFFFFFFFFu, x, off);
        if (threadIdx.x == 0) sh[0] = x;
    }
    __syncthreads();
    float r = sh[0];
    __syncthreads();
    return r;
}

// ---------------- K3: node masked-renorm softmax ----------------
__global__ void node_softmax(const float* __restrict__ mask_node,
                             float* __restrict__ d_out) {
    int b = blockIdx.x, t = threadIdx.x;  // 256 threads
    __shared__ float sh[32];
    float s = g_scores_node[b * NKN + t];
    float mk = mask_node[b * NKN + t];
    float m = blockReduceMax(s, sh, 8);
    float e = __expf(s - m) * mk;
    float sum = blockReduceSum(e, sh, 8);
    float a = e / sum;
    g_attn_node[b * NKN + t] = a;
    d_out[BB * HD + BB * TK + b * NKN + t] = a;   // attn_dist_node output
}

// ---------------- K4: gather + both token softmaxes + mix ----------------
__global__ void token_mix(const int* __restrict__ n2t,
                          const float* __restrict__ mask_tok,
                          float* __restrict__ d_out) {
    int b = blockIdx.x, t = threadIdx.x;  // 512 threads
    __shared__ float sh[32];
    float mk = mask_tok[b * TK + t];
    float sc = g_scores_tok[b * TK + t];
    int nidx = n2t[b * TK + t];
    float g = g_attn_node[b * NKN + nidx];

    float m1 = blockReduceMax(sc, sh, 16);
    float e1 = __expf(sc - m1) * mk;
    float s1 = blockReduceSum(e1, sh, 16);

    float m2 = blockReduceMax(g, sh, 16);
    float e2 = __expf(g - m2) * mk;
    float s2 = blockReduceSum(e2, sh, 16);

    float fin = 0.5f * (e1 / s1) + 0.5f * (e2 / s2);
    g_final[b * TK + t] = fin;
    d_out[BB * HD + b * TK + t] = fin;            // final_attn output
}

// ---------------- K5: c_t = final_attn @ enc_tok ----------------
__global__ void ctx_kernel(const float* __restrict__ enc_tok,
                           float* __restrict__ d_out) {
    int b = blockIdx.x, h = threadIdx.x;          // 512 threads, grid (B, 8)
    int t0 = blockIdx.y * 64;
    float acc = 0.f;
    #pragma unroll 8
    for (int t = t0; t < t0 + 64; t++)
        acc = fmaf(g_final[b * TK + t], enc_tok[((size_t)(b * TK + t)) * HD + h], acc);
    atomicAdd(&d_out[b * HD + h], acc);           // c_t output (zeroed in K0)
}

// ---------------- K6: graph diffusion ----------------
__global__ void hop1(const float* __restrict__ graph) {
    int b = blockIdx.x, m = threadIdx.x;          // 256 threads
    __shared__ float a[NKN];
    a[m] = g_attn_node[b * NKN + m];
    __syncthreads();
    float acc = 0.f;
    #pragma unroll 8
    for (int n = 0; n < NKN; n++)
        acc = fmaf(a[n], graph[(size_t)b * NKN * NKN + n * NKN + m], acc);
    g_one_hop[b * NKN + m] = acc;
}

__global__ void hop2(const float* __restrict__ graph,
                     float* __restrict__ d_out) {
    int b = blockIdx.x, m = threadIdx.x;          // 256 threads
    __shared__ float a[NKN];
    a[m] = g_one_hop[b * NKN + m];
    __syncthreads();
    float acc = 0.f;
    #pragma unroll 8
    for (int n = 0; n < NKN; n++)
        acc = fmaf(a[n], graph[(size_t)b * NKN * NKN + n * NKN + m], acc);
    float out = (g_attn_node[b * NKN + m] + a[m] + acc) * 0.33333f;
    d_out[BB * HD + BB * TK + BB * NKN + b * NKN + m] = out;   // flow_out
}

// ---------------- launch ----------------
extern "C" void kernel_launch(void* const* d_in, const int* in_sizes, int n_in,
                              void* d_out, int out_size) {
    const float* s_t_hat   = (const float*)d_in[0];   // [B, 2H]
    const float* enc_tok   = (const float*)d_in[1];   // [B, TK, H]
    const float* enc_node  = (const float*)d_in[2];   // [B, NK, H]
    const int*   n2t       = (const int*)  d_in[3];   // [B, TK]
    const float* mask_tok  = (const float*)d_in[4];   // [B, TK]
    const float* mask_node = (const float*)d_in[5];   // [B, NK]
    const float* graph     = (const float*)d_in[6];   // [B, NK, NK]
    const float* flow      = (const float*)d_in[7];   // [B, NK]
    const float* W_c       = (const float*)d_in[8];   // [H]
    const float* W_tok     = (const float*)d_in[9];   // [H, H]
    const float* W_node    = (const float*)d_in[10];  // [H, H]
    const float* W_dec     = (const float*)d_in[11];  // [2H, H]
    const float* b_dec     = (const float*)d_in[12];  // [H]
    const float* v_tok     = (const float*)d_in[13];  // [H]
    const float* v_node    = (const float*)d_in[14];  // [H]
    float* out = (float*)d_out;

    init_kernel<<<(BB * TK + BB * NKN + BB * HD) / 256, 256>>>(out);
    dec_kernel<<<BB, HD>>>(s_t_hat, W_dec, b_dec);

    gemm_score<0><<<dim3(HD / 64, (BB * TK) / 128), 256>>>(
        enc_tok, W_tok, nullptr, nullptr, v_tok, TK);
    gemm_score<1><<<dim3(HD / 64, (BB * NKN) / 128), 256>>>(
        enc_node, W_node, flow, W_c, v_node, NKN);

    node_softmax<<<BB, NKN>>>(mask_node, out);
    token_mix<<<BB, TK>>>(n2t, mask_tok, out);
    ctx_kernel<<<dim3(BB, 8), HD>>>(enc_tok, out);
    hop1<<<BB, NKN>>>(graph);
    hop2<<<BB, NKN>>>(graph, out);
}

// round 4
// speedup vs baseline: 2.6411x; 2.6411x over previous
#include <cuda_runtime.h>
#include <math.h>
#include <stdint.h>

#define HD 512
#define BB 64
#define TK 512
#define NKN 256

// -------- scratch (device globals: no allocations allowed) --------
__device__ float g_dec[BB * HD];
__device__ float g_scores_tok[BB * TK];
__device__ float g_scores_node[BB * NKN];
__device__ float g_attn_node[BB * NKN];
__device__ float g_final[BB * TK];
__device__ float g_one_hop[BB * NKN];

__device__ __forceinline__ float fast_tanh(float x) {
    float y;
    asm("tanh.approx.f32 %0, %1;" : "=f"(y) : "f"(x));
    return y;
}

__device__ __forceinline__ void cp16(uint32_t dst, const float* src) {
    asm volatile("cp.async.cg.shared.global [%0], [%1], 16;" :: "r"(dst), "l"(src));
}

// ---------------- K0: zero scratch + c_t output region ----------------
__global__ void init_kernel(float* __restrict__ d_out) {
    int i = blockIdx.x * blockDim.x + threadIdx.x;
    if (i < BB * TK) {
        g_scores_tok[i] = 0.f;
    } else if (i < BB * TK + BB * NKN) {
        g_scores_node[i - BB * TK] = 0.f;
    } else {
        int j = i - (BB * TK + BB * NKN);
        if (j < BB * HD) d_out[j] = 0.f;   // c_t region (atomicAdd target)
    }
}

// ---------------- K1: dec_fea = s_t_hat @ W_dec + b_dec ----------------
__global__ void dec_kernel(const float* __restrict__ s_t,
                           const float* __restrict__ Wd,
                           const float* __restrict__ bd) {
    int b = blockIdx.x;
    int h = threadIdx.x;              // blockDim = 512
    __shared__ float ss[2 * HD];
    for (int k = h; k < 2 * HD; k += HD) ss[k] = s_t[b * 2 * HD + k];
    __syncthreads();
    float acc = bd[h];
    #pragma unroll 8
    for (int k = 0; k < 2 * HD; k++) acc = fmaf(ss[k], Wd[k * HD + h], acc);
    g_dec[b * HD + h] = acc;
}

// ---------------- K2: tf32 mma.sync fused GEMM + tanh + v-dot ----------------
// scores[m] += sum_n v[n] * tanh( (A@W)[m,n] + dec[b,n] (+ flow[m]*Wc[n]) )
// CTA tile 128x128, BK=32, 2-stage cp.async, 8 warps of 64x32.
template <int NODE>
__global__ void __launch_bounds__(256, 2)
gemm_score_mma(const float* __restrict__ A,   // [M, 512] row-major
               const float* __restrict__ W,   // [512, 512] row-major ([K,N])
               const float* __restrict__ flw, // [M] (node only)
               const float* __restrict__ Wc,  // [512] (node only)
               const float* __restrict__ v,   // [512]
               int rows_per_batch) {
    const int BK = 32, KT = HD / BK;           // 16 k-tiles
    const int A_STRIDE = 36;                   // floats: conflict-free (4r+q)
    const int B_STRIDE = 136;                  // floats: conflict-free (8q+c)
    const int A_SZ = 128 * A_STRIDE;           // 4608 floats / stage
    const int B_SZ = BK * B_STRIDE;            // 4352 floats / stage

    extern __shared__ float sm[];
    float* As = sm;                 // 2 stages
    float* Bs = sm + 2 * A_SZ;      // 2 stages
    uint32_t sbase = (uint32_t)__cvta_generic_to_shared(sm);

    const int tid = threadIdx.x;
    const int lane = tid & 31, wid = tid >> 5;
    const int q = lane & 3, rr = lane >> 2;
    const int warp_m = wid & 1;        // 2 row groups of 64
    const int warp_n = wid >> 1;       // 4 col groups of 32
    const int m0 = blockIdx.y * 128, n0 = blockIdx.x * 128;

    float c[4][4][4];
    #pragma unroll
    for (int mt = 0; mt < 4; mt++)
        #pragma unroll
        for (int nt = 0; nt < 4; nt++)
            #pragma unroll
            for (int k = 0; k < 4; k++) c[mt][nt][k] = 0.f;

    auto load_stage = [&](int kt, int s) {
        const float* Ag = A + (size_t)m0 * HD + kt * BK;
        #pragma unroll
        for (int i = 0; i < 4; i++) {               // 128 rows x 8 x16B = 1024 chunks
            int idx = tid + i * 256;
            int r = idx >> 3, cc = idx & 7;
            cp16(sbase + (s * A_SZ + r * A_STRIDE + cc * 4) * 4,
                 Ag + (size_t)r * HD + cc * 4);
        }
        const float* Wg = W + (size_t)kt * BK * HD + n0;
        #pragma unroll
        for (int i = 0; i < 4; i++) {               // 32 rows x 32 x16B = 1024 chunks
            int idx = tid + i * 256;
            int r = idx >> 5, cc = idx & 31;
            cp16(sbase + (2 * A_SZ + s * B_SZ + r * B_STRIDE + cc * 4) * 4,
                 Wg + (size_t)r * HD + cc * 4);
        }
        asm volatile("cp.async.commit_group;" ::: "memory");
    };

    load_stage(0, 0);
    load_stage(1, 1);

    for (int kt = 0; kt < KT; kt++) {
        int s = kt & 1;
        if (kt < KT - 1) asm volatile("cp.async.wait_group 1;" ::: "memory");
        else             asm volatile("cp.async.wait_group 0;" ::: "memory");
        __syncthreads();

        const float* Ast = As + s * A_SZ;
        const float* Bst = Bs + s * B_SZ;

        #pragma unroll
        for (int k8 = 0; k8 < 4; k8++) {
            int k0 = k8 * 8;
            uint32_t b0[4], b1[4];
            #pragma unroll
            for (int nt = 0; nt < 4; nt++) {
                int col = warp_n * 32 + nt * 8 + rr;
                b0[nt] = __float_as_uint(Bst[(k0 + q) * B_STRIDE + col]);
                b1[nt] = __float_as_uint(Bst[(k0 + q + 4) * B_STRIDE + col]);
            }
            #pragma unroll
            for (int mt = 0; mt < 4; mt++) {
                int r = warp_m * 64 + mt * 16 + rr;
                uint32_t a0 = __float_as_uint(Ast[r * A_STRIDE + k0 + q]);
                uint32_t a1 = __float_as_uint(Ast[(r + 8) * A_STRIDE + k0 + q]);
                uint32_t a2 = __float_as_uint(Ast[r * A_STRIDE + k0 + q + 4]);
                uint32_t a3 = __float_as_uint(Ast[(r + 8) * A_STRIDE + k0 + q + 4]);
                #pragma unroll
                for (int nt = 0; nt < 4; nt++) {
                    asm volatile(
                        "mma.sync.aligned.m16n8k8.row.col.f32.tf32.tf32.f32 "
                        "{%0,%1,%2,%3}, {%4,%5,%6,%7}, {%8,%9}, {%0,%1,%2,%3};"
                        : "+f"(c[mt][nt][0]), "+f"(c[mt][nt][1]),
                          "+f"(c[mt][nt][2]), "+f"(c[mt][nt][3])
                        : "r"(a0), "r"(a1), "r"(a2), "r"(a3),
                          "r"(b0[nt]), "r"(b1[nt]));
                }
            }
        }
        __syncthreads();
        if (kt + 2 < KT) load_stage(kt + 2, s);
    }

    // ---- epilogue: tanh + v-dot, quad reduce, atomic partial scores ----
    float* scores = NODE ? g_scores_node : g_scores_tok;
    int b = m0 / rows_per_batch;

    // per-thread columns: 8 of them (4 nt x 2)
    float dv[8], vv[8], wc[8];
    #pragma unroll
    for (int nt = 0; nt < 4; nt++) {
        #pragma unroll
        for (int j = 0; j < 2; j++) {
            int n = n0 + warp_n * 32 + nt * 8 + 2 * q + j;
            dv[nt * 2 + j] = g_dec[b * HD + n];
            vv[nt * 2 + j] = v[n];
            wc[nt * 2 + j] = NODE ? Wc[n] : 0.f;
        }
    }

    #pragma unroll
    for (int mt = 0; mt < 4; mt++) {
        int r = m0 + warp_m * 64 + mt * 16 + rr;
        float fl0 = NODE ? flw[r] : 0.f;
        float fl1 = NODE ? flw[r + 8] : 0.f;
        float rs0 = 0.f, rs1 = 0.f;
        #pragma unroll
        for (int nt = 0; nt < 4; nt++) {
            #pragma unroll
            for (int j = 0; j < 2; j++) {
                int e = nt * 2 + j;
                float v0 = c[mt][nt][j] + dv[e];
                float v1 = c[mt][nt][2 + j] + dv[e];
                if (NODE) { v0 = fmaf(fl0, wc[e], v0); v1 = fmaf(fl1, wc[e], v1); }
                rs0 += vv[e] * fast_tanh(v0);
                rs1 += vv[e] * fast_tanh(v1);
            }
        }
        rs0 += __shfl_xor_sync(0xFFFFFFFFu, rs0, 1, 4);
        rs0 += __shfl_xor_sync(0xFFFFFFFFu, rs0, 2, 4);
        rs1 += __shfl_xor_sync(0xFFFFFFFFu, rs1, 1, 4);
        rs1 += __shfl_xor_sync(0xFFFFFFFFu, rs1, 2, 4);
        if (q == 0) {
            atomicAdd(&scores[r], rs0);
            atomicAdd(&scores[r + 8], rs1);
        }
    }
}

// ---------------- block reduce helpers ----------------
__device__ __forceinline__ float blockReduceMax(float v, float* sh, int nwarp) {
    #pragma unroll
    for (int off = 16; off > 0; off >>= 1)
        v = fmaxf(v, __shfl_xor_sync(0xFFFFFFFFu, v, off));
    int lane = threadIdx.x & 31, w = threadIdx.x >> 5;
    if (lane == 0) sh[w] = v;
    __syncthreads();
    if (threadIdx.x < 32) {
        float x = (threadIdx.x < nwarp) ? sh[threadIdx.x] : -INFINITY;
        #pragma unroll
        for (int off = 16; off > 0; off >>= 1)
            x = fmaxf(x, __shfl_xor_sync(0xFFFFFFFFu, x, off));
        if (threadIdx.x == 0) sh[0] = x;
    }
    __syncthreads();
    float r = sh[0];
    __syncthreads();
    return r;
}

__device__ __forceinline__ float blockReduceSum(float v, float* sh, int nwarp) {
    #pragma unroll
    for (int off = 16; off > 0; off >>= 1)
        v += __shfl_xor_sync(0xFFFFFFFFu, v, off);
    int lane = threadIdx.x & 31, w = threadIdx.x >> 5;
    if (lane == 0) sh[w] = v;
    __syncthreads();
    if (threadIdx.x < 32) {
        float x = (threadIdx.x < nwarp) ? sh[threadIdx.x] : 0.f;
        #pragma unroll
        for (int off = 16; off > 0; off >>= 1)
            x += __shfl_xor_sync(0xFFFFFFFFu, x, off);
        if (threadIdx.x == 0) sh[0] = x;
    }
    __syncthreads();
    float r = sh[0];
    __syncthreads();
    return r;
}

// ---------------- K3: node masked-renorm softmax ----------------
__global__ void node_softmax(const float* __restrict__ mask_node,
                             float* __restrict__ d_out) {
    int b = blockIdx.x, t = threadIdx.x;  // 256 threads
    __shared__ float sh[32];
    float s = g_scores_node[b * NKN + t];
    float mk = mask_node[b * NKN + t];
    float m = blockReduceMax(s, sh, 8);
    float e = __expf(s - m) * mk;
    float sum = blockReduceSum(e, sh, 8);
    float a = e / sum;
    g_attn_node[b * NKN + t] = a;
    d_out[BB * HD + BB * TK + b * NKN + t] = a;   // attn_dist_node output
}

// ---------------- K4: gather + both token softmaxes + mix ----------------
__global__ void token_mix(const int* __restrict__ n2t,
                          const float* __restrict__ mask_tok,
                          float* __restrict__ d_out) {
    int b = blockIdx.x, t = threadIdx.x;  // 512 threads
    __shared__ float sh[32];
    float mk = mask_tok[b * TK + t];
    float sc = g_scores_tok[b * TK + t];
    int nidx = n2t[b * TK + t];
    float g = g_attn_node[b * NKN + nidx];

    float m1 = blockReduceMax(sc, sh, 16);
    float e1 = __expf(sc - m1) * mk;
    float s1 = blockReduceSum(e1, sh, 16);

    float m2 = blockReduceMax(g, sh, 16);
    float e2 = __expf(g - m2) * mk;
    float s2 = blockReduceSum(e2, sh, 16);

    float fin = 0.5f * (e1 / s1) + 0.5f * (e2 / s2);
    g_final[b * TK + t] = fin;
    d_out[BB * HD + b * TK + t] = fin;            // final_attn output
}

// ---------------- K5: c_t = final_attn @ enc_tok ----------------
__global__ void ctx_kernel(const float* __restrict__ enc_tok,
                           float* __restrict__ d_out) {
    int b = blockIdx.x, h = threadIdx.x;          // 512 threads, grid (B, 8)
    int t0 = blockIdx.y * 64;
    float acc = 0.f;
    #pragma unroll 8
    for (int t = t0; t < t0 + 64; t++)
        acc = fmaf(g_final[b * TK + t], enc_tok[((size_t)(b * TK + t)) * HD + h], acc);
    atomicAdd(&d_out[b * HD + h], acc);           // c_t output (zeroed in K0)
}

// ---------------- K6: graph diffusion ----------------
__global__ void hop1(const float* __restrict__ graph) {
    int b = blockIdx.x, m = threadIdx.x;          // 256 threads
    __shared__ float a[NKN];
    a[m] = g_attn_node[b * NKN + m];
    __syncthreads();
    float acc = 0.f;
    #pragma unroll 8
    for (int n = 0; n < NKN; n++)
        acc = fmaf(a[n], graph[(size_t)b * NKN * NKN + n * NKN + m], acc);
    g_one_hop[b * NKN + m] = acc;
}

__global__ void hop2(const float* __restrict__ graph,
                     float* __restrict__ d_out) {
    int b = blockIdx.x, m = threadIdx.x;          // 256 threads
    __shared__ float a[NKN];
    a[m] = g_one_hop[b * NKN + m];
    __syncthreads();
    float acc = 0.f;
    #pragma unroll 8
    for (int n = 0; n < NKN; n++)
        acc = fmaf(a[n], graph[(size_t)b * NKN * NKN + n * NKN + m], acc);
    float out = (g_attn_node[b * NKN + m] + a[m] + acc) * 0.33333f;
    d_out[BB * HD + BB * TK + BB * NKN + b * NKN + m] = out;   // flow_out
}

// ---------------- launch ----------------
extern "C" void kernel_launch(void* const* d_in, const int* in_sizes, int n_in,
                              void* d_out, int out_size) {
    const float* s_t_hat   = (const float*)d_in[0];
    const float* enc_tok   = (const float*)d_in[1];
    const float* enc_node  = (const float*)d_in[2];
    const int*   n2t       = (const int*)  d_in[3];
    const float* mask_tok  = (const float*)d_in[4];
    const float* mask_node = (const float*)d_in[5];
    const float* graph     = (const float*)d_in[6];
    const float* flow      = (const float*)d_in[7];
    const float* W_c       = (const float*)d_in[8];
    const float* W_tok     = (const float*)d_in[9];
    const float* W_node    = (const float*)d_in[10];
    const float* W_dec     = (const float*)d_in[11];
    const float* b_dec     = (const float*)d_in[12];
    const float* v_tok     = (const float*)d_in[13];
    const float* v_node    = (const float*)d_in[14];
    float* out = (float*)d_out;

    const int SMEM_BYTES = (2 * 128 * 36 + 2 * 32 * 136) * 4;   // 71680
    static bool attr_set = false;
    if (!attr_set) {
        cudaFuncSetAttribute(gemm_score_mma<0>,
                             cudaFuncAttributeMaxDynamicSharedMemorySize, SMEM_BYTES);
        cudaFuncSetAttribute(gemm_score_mma<1>,
                             cudaFuncAttributeMaxDynamicSharedMemorySize, SMEM_BYTES);
        attr_set = true;
    }

    init_kernel<<<(BB * TK + BB * NKN + BB * HD) / 256, 256>>>(out);
    dec_kernel<<<BB, HD>>>(s_t_hat, W_dec, b_dec);

    gemm_score_mma<0><<<dim3(HD / 128, (BB * TK) / 128), 256, SMEM_BYTES>>>(
        enc_tok, W_tok, nullptr, nullptr, v_tok, TK);
    gemm_score_mma<1><<<dim3(HD / 128, (BB * NKN) / 128), 256, SMEM_BYTES>>>(
        enc_node, W_node, flow, W_c, v_node, NKN);

    node_softmax<<<BB, NKN>>>(mask_node, out);
    token_mix<<<BB, TK>>>(n2t, mask_tok, out);
    ctx_kernel<<<dim3(BB, 8), HD>>>(enc_tok, out);
    hop1<<<BB, NKN>>>(graph);
    hop2<<<BB, NKN>>>(graph, out);
}

// round 5
// speedup vs baseline: 2.6581x; 1.0065x over previous
#include <cuda_runtime.h>
#include <math.h>
#include <stdint.h>

#define HD 512
#define BB 64
#define TK 512
#define NKN 256

// -------- scratch (device globals: no allocations allowed) --------
__device__ float g_dec[BB * HD];
__device__ float g_scores_tok[BB * TK];
__device__ float g_scores_node[BB * NKN];
__device__ float g_attn_node[BB * NKN];
__device__ float g_final[BB * TK];
__device__ float g_one_hop[BB * NKN];

__device__ __forceinline__ float fast_tanh(float x) {
    float y;
    asm("tanh.approx.f32 %0, %1;" : "=f"(y) : "f"(x));
    return y;
}

__device__ __forceinline__ void cp16(uint32_t dst, const float* src) {
    asm volatile("cp.async.cg.shared.global [%0], [%1], 16;" :: "r"(dst), "l"(src));
}

// ---------------- K0: zero scratch + c_t output region ----------------
__global__ void init_kernel(float* __restrict__ d_out) {
    int i = blockIdx.x * blockDim.x + threadIdx.x;
    if (i < BB * TK) {
        g_scores_tok[i] = 0.f;
    } else if (i < BB * TK + BB * NKN) {
        g_scores_node[i - BB * TK] = 0.f;
    } else {
        int j = i - (BB * TK + BB * NKN);
        if (j < BB * HD) d_out[j] = 0.f;   // c_t region (atomicAdd target)
    }
}

// ---------------- K1: dec_fea = s_t_hat @ W_dec + b_dec ----------------
__global__ void dec_kernel(const float* __restrict__ s_t,
                           const float* __restrict__ Wd,
                           const float* __restrict__ bd) {
    int b = blockIdx.x;
    int h = threadIdx.x;              // blockDim = 512
    __shared__ float ss[2 * HD];
    for (int k = h; k < 2 * HD; k += HD) ss[k] = s_t[b * 2 * HD + k];
    __syncthreads();
    float acc = bd[h];
    #pragma unroll 8
    for (int k = 0; k < 2 * HD; k++) acc = fmaf(ss[k], Wd[k * HD + h], acc);
    g_dec[b * HD + h] = acc;
}

// ---------------- K2: fused tf32 GEMM (token+node) + tanh + v-dot ----------------
// grid = (4, 384): by<256 -> token M-tiles, by>=256 -> node M-tiles.
// CTA tile 128x128, BK=32, 3-stage cp.async ring, 1 sync per k-tile.
__global__ void __launch_bounds__(256, 2)
gemm_score_fused(const float* __restrict__ A_tok,   // [B*TK, 512]
                 const float* __restrict__ A_node,  // [B*NK, 512]
                 const float* __restrict__ W_tok,   // [512, 512]
                 const float* __restrict__ W_node,  // [512, 512]
                 const float* __restrict__ flw,     // [B*NK]
                 const float* __restrict__ Wc,      // [512]
                 const float* __restrict__ v_tok,   // [512]
                 const float* __restrict__ v_node)  // [512]
{
    const int BK = 32, KT = HD / BK;           // 16 k-tiles
    const int STG = 3;
    const int A_STRIDE = 36;                   // floats: conflict-free (4r+q)
    const int B_STRIDE = 136;                  // floats: conflict-free (8q+c)
    const int A_SZ = 128 * A_STRIDE;           // 4608 floats / stage
    const int B_SZ = BK * B_STRIDE;            // 4352 floats / stage
    const int STG_SZ = A_SZ + B_SZ;            // 8960 floats

    extern __shared__ float sm[];
    uint32_t sbase = (uint32_t)__cvta_generic_to_shared(sm);

    const int tid = threadIdx.x;
    const int lane = tid & 31, wid = tid >> 5;
    const int q = lane & 3, rr = lane >> 2;
    const int warp_m = wid & 1;        // 2 row groups of 64
    const int warp_n = wid >> 1;       // 4 col groups of 32
    const bool node = blockIdx.y >= 256;
    const int m0 = node ? (blockIdx.y - 256) * 128 : blockIdx.y * 128;
    const int n0 = blockIdx.x * 128;

    const float* A = node ? A_node : A_tok;
    const float* W = node ? W_node : W_tok;

    float c[4][4][4];
    #pragma unroll
    for (int mt = 0; mt < 4; mt++)
        #pragma unroll
        for (int nt = 0; nt < 4; nt++)
            #pragma unroll
            for (int k = 0; k < 4; k++) c[mt][nt][k] = 0.f;

    auto load_stage = [&](int kt, int s) {
        uint32_t sb = sbase + s * STG_SZ * 4;
        const float* Ag = A + (size_t)m0 * HD + kt * BK;
        #pragma unroll
        for (int i = 0; i < 4; i++) {               // 128 rows x 8 x16B
            int idx = tid + i * 256;
            int r = idx >> 3, cc = idx & 7;
            cp16(sb + (r * A_STRIDE + cc * 4) * 4, Ag + (size_t)r * HD + cc * 4);
        }
        const float* Wg = W + (size_t)kt * BK * HD + n0;
        #pragma unroll
        for (int i = 0; i < 4; i++) {               // 32 rows x 32 x16B
            int idx = tid + i * 256;
            int r = idx >> 5, cc = idx & 31;
            cp16(sb + (A_SZ + r * B_STRIDE + cc * 4) * 4, Wg + (size_t)r * HD + cc * 4);
        }
        asm volatile("cp.async.commit_group;" ::: "memory");
    };

    load_stage(0, 0);
    load_stage(1, 1);

    for (int kt = 0; kt < KT; kt++) {
        int s = kt % STG;
        if (kt < KT - 1) asm volatile("cp.async.wait_group 1;" ::: "memory");
        else             asm volatile("cp.async.wait_group 0;" ::: "memory");
        __syncthreads();
        if (kt + 2 < KT) load_stage(kt + 2, (kt + 2) % STG);

        const float* Ast = sm + s * STG_SZ;
        const float* Bst = Ast + A_SZ;

        #pragma unroll
        for (int k8 = 0; k8 < 4; k8++) {
            int k0 = k8 * 8;
            uint32_t b0[4], b1[4];
            #pragma unroll
            for (int nt = 0; nt < 4; nt++) {
                int col = warp_n * 32 + nt * 8 + rr;
                b0[nt] = __float_as_uint(Bst[(k0 + q) * B_STRIDE + col]);
                b1[nt] = __float_as_uint(Bst[(k0 + q + 4) * B_STRIDE + col]);
            }
            #pragma unroll
            for (int mt = 0; mt < 4; mt++) {
                int r = warp_m * 64 + mt * 16 + rr;
                uint32_t a0 = __float_as_uint(Ast[r * A_STRIDE + k0 + q]);
                uint32_t a1 = __float_as_uint(Ast[(r + 8) * A_STRIDE + k0 + q]);
                uint32_t a2 = __float_as_uint(Ast[r * A_STRIDE + k0 + q + 4]);
                uint32_t a3 = __float_as_uint(Ast[(r + 8) * A_STRIDE + k0 + q + 4]);
                #pragma unroll
                for (int nt = 0; nt < 4; nt++) {
                    asm volatile(
                        "mma.sync.aligned.m16n8k8.row.col.f32.tf32.tf32.f32 "
                        "{%0,%1,%2,%3}, {%4,%5,%6,%7}, {%8,%9}, {%0,%1,%2,%3};"
                        : "+f"(c[mt][nt][0]), "+f"(c[mt][nt][1]),
                          "+f"(c[mt][nt][2]), "+f"(c[mt][nt][3])
                        : "r"(a0), "r"(a1), "r"(a2), "r"(a3),
                          "r"(b0[nt]), "r"(b1[nt]));
                }
            }
        }
    }

    // ---- epilogue: tanh + v-dot, quad reduce, atomic partial scores ----
    float* scores = node ? g_scores_node : g_scores_tok;
    const float* v = node ? v_node : v_tok;
    int b = node ? (m0 / NKN) : (m0 / TK);

    float dv[8], vv[8], wc[8];
    #pragma unroll
    for (int nt = 0; nt < 4; nt++) {
        #pragma unroll
        for (int j = 0; j < 2; j++) {
            int n = n0 + warp_n * 32 + nt * 8 + 2 * q + j;
            dv[nt * 2 + j] = g_dec[b * HD + n];
            vv[nt * 2 + j] = v[n];
            wc[nt * 2 + j] = node ? Wc[n] : 0.f;
        }
    }

    #pragma unroll
    for (int mt = 0; mt < 4; mt++) {
        int r = m0 + warp_m * 64 + mt * 16 + rr;
        float fl0 = node ? flw[r] : 0.f;
        float fl1 = node ? flw[r + 8] : 0.f;
        float rs0 = 0.f, rs1 = 0.f;
        #pragma unroll
        for (int nt = 0; nt < 4; nt++) {
            #pragma unroll
            for (int j = 0; j < 2; j++) {
                int e = nt * 2 + j;
                float v0 = fmaf(fl0, wc[e], c[mt][nt][j] + dv[e]);
                float v1 = fmaf(fl1, wc[e], c[mt][nt][2 + j] + dv[e]);
                rs0 += vv[e] * fast_tanh(v0);
                rs1 += vv[e] * fast_tanh(v1);
            }
        }
        rs0 += __shfl_xor_sync(0xFFFFFFFFu, rs0, 1, 4);
        rs0 += __shfl_xor_sync(0xFFFFFFFFu, rs0, 2, 4);
        rs1 += __shfl_xor_sync(0xFFFFFFFFu, rs1, 1, 4);
        rs1 += __shfl_xor_sync(0xFFFFFFFFu, rs1, 2, 4);
        if (q == 0) {
            atomicAdd(&scores[r], rs0);
            atomicAdd(&scores[r + 8], rs1);
        }
    }
}

// ---------------- block reduce helpers ----------------
__device__ __forceinline__ float blockReduceMax(float v, float* sh, int nwarp) {
    #pragma unroll
    for (int off = 16; off > 0; off >>= 1)
        v = fmaxf(v, __shfl_xor_sync(0xFFFFFFFFu, v, off));
    int lane = threadIdx.x & 31, w = threadIdx.x >> 5;
    if (lane == 0) sh[w] = v;
    __syncthreads();
    if (threadIdx.x < 32) {
        float x = (threadIdx.x < nwarp) ? sh[threadIdx.x] : -INFINITY;
        #pragma unroll
        for (int off = 16; off > 0; off >>= 1)
            x = fmaxf(x, __shfl_xor_sync(0xFFFFFFFFu, x, off));
        if (threadIdx.x == 0) sh[0] = x;
    }
    __syncthreads();
    float r = sh[0];
    __syncthreads();
    return r;
}

__device__ __forceinline__ float blockReduceSum(float v, float* sh, int nwarp) {
    #pragma unroll
    for (int off = 16; off > 0; off >>= 1)
        v += __shfl_xor_sync(0xFFFFFFFFu, v, off);
    int lane = threadIdx.x & 31, w = threadIdx.x >> 5;
    if (lane == 0) sh[w] = v;
    __syncthreads();
    if (threadIdx.x < 32) {
        float x = (threadIdx.x < nwarp) ? sh[threadIdx.x] : 0.f;
        #pragma unroll
        for (int off = 16; off > 0; off >>= 1)
            x += __shfl_xor_sync(0xFFFFFFFFu, x, off);
        if (threadIdx.x == 0) sh[0] = x;
    }
    __syncthreads();
    float r = sh[0];
    __syncthreads();
    return r;
}

// ---------------- K3: node masked-renorm softmax ----------------
__global__ void node_softmax(const float* __restrict__ mask_node,
                             float* __restrict__ d_out) {
    int b = blockIdx.x, t = threadIdx.x;  // 256 threads
    __shared__ float sh[32];
    float s = g_scores_node[b * NKN + t];
    float mk = mask_node[b * NKN + t];
    float m = blockReduceMax(s, sh, 8);
    float e = __expf(s - m) * mk;
    float sum = blockReduceSum(e, sh, 8);
    float a = e / sum;
    g_attn_node[b * NKN + t] = a;
    d_out[BB * HD + BB * TK + b * NKN + t] = a;   // attn_dist_node output
}

// ---------------- K4: gather + both token softmaxes + mix ----------------
__global__ void token_mix(const int* __restrict__ n2t,
                          const float* __restrict__ mask_tok,
                          float* __restrict__ d_out) {
    int b = blockIdx.x, t = threadIdx.x;  // 512 threads
    __shared__ float sh[32];
    float mk = mask_tok[b * TK + t];
    float sc = g_scores_tok[b * TK + t];
    int nidx = n2t[b * TK + t];
    float g = g_attn_node[b * NKN + nidx];

    float m1 = blockReduceMax(sc, sh, 16);
    float e1 = __expf(sc - m1) * mk;
    float s1 = blockReduceSum(e1, sh, 16);

    float m2 = blockReduceMax(g, sh, 16);
    float e2 = __expf(g - m2) * mk;
    float s2 = blockReduceSum(e2, sh, 16);

    float fin = 0.5f * (e1 / s1) + 0.5f * (e2 / s2);
    g_final[b * TK + t] = fin;
    d_out[BB * HD + b * TK + t] = fin;            // final_attn output
}

// ---------------- K5: c_t = final_attn @ enc_tok ----------------
__global__ void ctx_kernel(const float* __restrict__ enc_tok,
                           float* __restrict__ d_out) {
    int b = blockIdx.x, h = threadIdx.x;          // 512 threads, grid (B, 8)
    int t0 = blockIdx.y * 64;
    float acc = 0.f;
    #pragma unroll 8
    for (int t = t0; t < t0 + 64; t++)
        acc = fmaf(g_final[b * TK + t], enc_tok[((size_t)(b * TK + t)) * HD + h], acc);
    atomicAdd(&d_out[b * HD + h], acc);           // c_t output (zeroed in K0)
}

// ---------------- K6: graph diffusion ----------------
__global__ void hop1(const float* __restrict__ graph) {
    int b = blockIdx.x, m = threadIdx.x;          // 256 threads
    __shared__ float a[NKN];
    a[m] = g_attn_node[b * NKN + m];
    __syncthreads();
    float acc = 0.f;
    #pragma unroll 8
    for (int n = 0; n < NKN; n++)
        acc = fmaf(a[n], graph[(size_t)b * NKN * NKN + n * NKN + m], acc);
    g_one_hop[b * NKN + m] = acc;
}

__global__ void hop2(const float* __restrict__ graph,
                     float* __restrict__ d_out) {
    int b = blockIdx.x, m = threadIdx.x;          // 256 threads
    __shared__ float a[NKN];
    a[m] = g_one_hop[b * NKN + m];
    __syncthreads();
    float acc = 0.f;
    #pragma unroll 8
    for (int n = 0; n < NKN; n++)
        acc = fmaf(a[n], graph[(size_t)b * NKN * NKN + n * NKN + m], acc);
    float out = (g_attn_node[b * NKN + m] + a[m] + acc) * 0.33333f;
    d_out[BB * HD + BB * TK + BB * NKN + b * NKN + m] = out;   // flow_out
}

// ---------------- launch ----------------
extern "C" void kernel_launch(void* const* d_in, const int* in_sizes, int n_in,
                              void* d_out, int out_size) {
    const float* s_t_hat   = (const float*)d_in[0];
    const float* enc_tok   = (const float*)d_in[1];
    const float* enc_node  = (const float*)d_in[2];
    const int*   n2t       = (const int*)  d_in[3];
    const float* mask_tok  = (const float*)d_in[4];
    const float* mask_node = (const float*)d_in[5];
    const float* graph     = (const float*)d_in[6];
    const float* flow      = (const float*)d_in[7];
    const float* W_c       = (const float*)d_in[8];
    const float* W_tok     = (const float*)d_in[9];
    const float* W_node    = (const float*)d_in[10];
    const float* W_dec     = (const float*)d_in[11];
    const float* b_dec     = (const float*)d_in[12];
    const float* v_tok     = (const float*)d_in[13];
    const float* v_node    = (const float*)d_in[14];
    float* out = (float*)d_out;

    const int SMEM_BYTES = 3 * (128 * 36 + 32 * 136) * 4;   // 107520
    static bool attr_set = false;
    if (!attr_set) {
        cudaFuncSetAttribute(gemm_score_fused,
                             cudaFuncAttributeMaxDynamicSharedMemorySize, SMEM_BYTES);
        attr_set = true;
    }

    init_kernel<<<(BB * TK + BB * NKN + BB * HD) / 256, 256>>>(out);
    dec_kernel<<<BB, HD>>>(s_t_hat, W_dec, b_dec);

    gemm_score_fused<<<dim3(HD / 128, 384), 256, SMEM_BYTES>>>(
        enc_tok, enc_node, W_tok, W_node, flow, W_c, v_tok, v_node);

    node_softmax<<<BB, NKN>>>(mask_node, out);
    token_mix<<<BB, TK>>>(n2t, mask_tok, out);
    ctx_kernel<<<dim3(BB, 8), HD>>>(enc_tok, out);
    hop1<<<BB, NKN>>>(graph);
    hop2<<<BB, NKN>>>(graph, out);
}

// round 6
// speedup vs baseline: 2.7426x; 1.0318x over previous
#include <cuda_runtime.h>
#include <math.h>
#include <stdint.h>

#define HD 512
#define BB 64
#define TK 512
#define NKN 256

// -------- scratch (device globals: no allocations allowed) --------
__device__ float g_dec[BB * HD];
__device__ float g_scores_tok[BB * TK];
__device__ float g_scores_node[BB * NKN];
__device__ float g_final[BB * TK];

__device__ __forceinline__ float fast_tanh(float x) {
    float y;
    asm("tanh.approx.f32 %0, %1;" : "=f"(y) : "f"(x));
    return y;
}

__device__ __forceinline__ void cp16(uint32_t dst, const float* src) {
    asm volatile("cp.async.cg.shared.global [%0], [%1], 16;" :: "r"(dst), "l"(src));
}

// ---------------- K1: dec_fea + zero scratch/c_t  (grid BB, block 512) --------
__global__ void dec_init_kernel(const float* __restrict__ s_t,
                                const float* __restrict__ Wd,
                                const float* __restrict__ bd,
                                float* __restrict__ d_out) {
    int b = blockIdx.x;
    int h = threadIdx.x;              // blockDim = 512
    // zeroing (atomicAdd targets)
    g_scores_tok[b * TK + h] = 0.f;
    if (h < NKN) g_scores_node[b * NKN + h] = 0.f;
    d_out[b * HD + h] = 0.f;          // c_t region

    __shared__ float ss[2 * HD];
    for (int k = h; k < 2 * HD; k += HD) ss[k] = s_t[b * 2 * HD + k];
    __syncthreads();
    float acc = bd[h];
    #pragma unroll 8
    for (int k = 0; k < 2 * HD; k++) acc = fmaf(ss[k], Wd[k * HD + h], acc);
    g_dec[b * HD + h] = acc;
}

// ---------------- K2: fused tf32 GEMM (token+node) + tanh + v-dot ----------------
// grid = (4, 384): by<256 -> token M-tiles, by>=256 -> node M-tiles.
// CTA tile 128x128, BK=32, 3-stage cp.async ring, 1 sync per k-tile.
__global__ void __launch_bounds__(256, 2)
gemm_score_fused(const float* __restrict__ A_tok,   // [B*TK, 512]
                 const float* __restrict__ A_node,  // [B*NK, 512]
                 const float* __restrict__ W_tok,   // [512, 512]
                 const float* __restrict__ W_node,  // [512, 512]
                 const float* __restrict__ flw,     // [B*NK]
                 const float* __restrict__ Wc,      // [512]
                 const float* __restrict__ v_tok,   // [512]
                 const float* __restrict__ v_node)  // [512]
{
    const int BK = 32, KT = HD / BK;           // 16 k-tiles
    const int STG = 3;
    const int A_STRIDE = 36;                   // floats: conflict-free (4r+q)
    const int B_STRIDE = 136;                  // floats: conflict-free (8q+c)
    const int A_SZ = 128 * A_STRIDE;           // 4608 floats / stage
    const int B_SZ = BK * B_STRIDE;            // 4352 floats / stage
    const int STG_SZ = A_SZ + B_SZ;            // 8960 floats

    extern __shared__ float sm[];
    uint32_t sbase = (uint32_t)__cvta_generic_to_shared(sm);

    const int tid = threadIdx.x;
    const int lane = tid & 31, wid = tid >> 5;
    const int q = lane & 3, rr = lane >> 2;
    const int warp_m = wid & 1;        // 2 row groups of 64
    const int warp_n = wid >> 1;       // 4 col groups of 32
    const bool node = blockIdx.y >= 256;
    const int m0 = node ? (blockIdx.y - 256) * 128 : blockIdx.y * 128;
    const int n0 = blockIdx.x * 128;

    const float* A = node ? A_node : A_tok;
    const float* W = node ? W_node : W_tok;

    float c[4][4][4];
    #pragma unroll
    for (int mt = 0; mt < 4; mt++)
        #pragma unroll
        for (int nt = 0; nt < 4; nt++)
            #pragma unroll
            for (int k = 0; k < 4; k++) c[mt][nt][k] = 0.f;

    auto load_stage = [&](int kt, int s) {
        uint32_t sb = sbase + s * STG_SZ * 4;
        const float* Ag = A + (size_t)m0 * HD + kt * BK;
        #pragma unroll
        for (int i = 0; i < 4; i++) {               // 128 rows x 8 x16B
            int idx = tid + i * 256;
            int r = idx >> 3, cc = idx & 7;
            cp16(sb + (r * A_STRIDE + cc * 4) * 4, Ag + (size_t)r * HD + cc * 4);
        }
        const float* Wg = W + (size_t)kt * BK * HD + n0;
        #pragma unroll
        for (int i = 0; i < 4; i++) {               // 32 rows x 32 x16B
            int idx = tid + i * 256;
            int r = idx >> 5, cc = idx & 31;
            cp16(sb + (A_SZ + r * B_STRIDE + cc * 4) * 4, Wg + (size_t)r * HD + cc * 4);
        }
        asm volatile("cp.async.commit_group;" ::: "memory");
    };

    load_stage(0, 0);
    load_stage(1, 1);

    for (int kt = 0; kt < KT; kt++) {
        int s = kt % STG;
        if (kt < KT - 1) asm volatile("cp.async.wait_group 1;" ::: "memory");
        else             asm volatile("cp.async.wait_group 0;" ::: "memory");
        __syncthreads();
        if (kt + 2 < KT) load_stage(kt + 2, (kt + 2) % STG);

        const float* Ast = sm + s * STG_SZ;
        const float* Bst = Ast + A_SZ;

        #pragma unroll
        for (int k8 = 0; k8 < 4; k8++) {
            int k0 = k8 * 8;
            uint32_t b0[4], b1[4];
            #pragma unroll
            for (int nt = 0; nt < 4; nt++) {
                int col = warp_n * 32 + nt * 8 + rr;
                b0[nt] = __float_as_uint(Bst[(k0 + q) * B_STRIDE + col]);
                b1[nt] = __float_as_uint(Bst[(k0 + q + 4) * B_STRIDE + col]);
            }
            #pragma unroll
            for (int mt = 0; mt < 4; mt++) {
                int r = warp_m * 64 + mt * 16 + rr;
                uint32_t a0 = __float_as_uint(Ast[r * A_STRIDE + k0 + q]);
                uint32_t a1 = __float_as_uint(Ast[(r + 8) * A_STRIDE + k0 + q]);
                uint32_t a2 = __float_as_uint(Ast[r * A_STRIDE + k0 + q + 4]);
                uint32_t a3 = __float_as_uint(Ast[(r + 8) * A_STRIDE + k0 + q + 4]);
                #pragma unroll
                for (int nt = 0; nt < 4; nt++) {
                    asm volatile(
                        "mma.sync.aligned.m16n8k8.row.col.f32.tf32.tf32.f32 "
                        "{%0,%1,%2,%3}, {%4,%5,%6,%7}, {%8,%9}, {%0,%1,%2,%3};"
                        : "+f"(c[mt][nt][0]), "+f"(c[mt][nt][1]),
                          "+f"(c[mt][nt][2]), "+f"(c[mt][nt][3])
                        : "r"(a0), "r"(a1), "r"(a2), "r"(a3),
                          "r"(b0[nt]), "r"(b1[nt]));
                }
            }
        }
    }

    // ---- epilogue: tanh + v-dot, quad reduce, atomic partial scores ----
    float* scores = node ? g_scores_node : g_scores_tok;
    const float* v = node ? v_node : v_tok;
    int b = node ? (m0 / NKN) : (m0 / TK);

    float dv[8], vv[8], wc[8];
    #pragma unroll
    for (int nt = 0; nt < 4; nt++) {
        #pragma unroll
        for (int j = 0; j < 2; j++) {
            int n = n0 + warp_n * 32 + nt * 8 + 2 * q + j;
            dv[nt * 2 + j] = g_dec[b * HD + n];
            vv[nt * 2 + j] = v[n];
            wc[nt * 2 + j] = node ? Wc[n] : 0.f;
        }
    }

    #pragma unroll
    for (int mt = 0; mt < 4; mt++) {
        int r = m0 + warp_m * 64 + mt * 16 + rr;
        float fl0 = node ? flw[r] : 0.f;
        float fl1 = node ? flw[r + 8] : 0.f;
        float rs0 = 0.f, rs1 = 0.f;
        #pragma unroll
        for (int nt = 0; nt < 4; nt++) {
            #pragma unroll
            for (int j = 0; j < 2; j++) {
                int e = nt * 2 + j;
                float v0 = fmaf(fl0, wc[e], c[mt][nt][j] + dv[e]);
                float v1 = fmaf(fl1, wc[e], c[mt][nt][2 + j] + dv[e]);
                rs0 += vv[e] * fast_tanh(v0);
                rs1 += vv[e] * fast_tanh(v1);
            }
        }
        rs0 += __shfl_xor_sync(0xFFFFFFFFu, rs0, 1, 4);
        rs0 += __shfl_xor_sync(0xFFFFFFFFu, rs0, 2, 4);
        rs1 += __shfl_xor_sync(0xFFFFFFFFu, rs1, 1, 4);
        rs1 += __shfl_xor_sync(0xFFFFFFFFu, rs1, 2, 4);
        if (q == 0) {
            atomicAdd(&scores[r], rs0);
            atomicAdd(&scores[r + 8], rs1);
        }
    }
}

// ---------------- block reduce helpers (512 threads) ----------------
__device__ __forceinline__ float blockReduceMax512(float v, float* sh) {
    #pragma unroll
    for (int off = 16; off > 0; off >>= 1)
        v = fmaxf(v, __shfl_xor_sync(0xFFFFFFFFu, v, off));
    int lane = threadIdx.x & 31, w = threadIdx.x >> 5;
    if (lane == 0) sh[w] = v;
    __syncthreads();
    if (threadIdx.x < 32) {
        float x = (threadIdx.x < 16) ? sh[threadIdx.x] : -INFINITY;
        #pragma unroll
        for (int off = 8; off > 0; off >>= 1)
            x = fmaxf(x, __shfl_xor_sync(0xFFFFFFFFu, x, off));
        if (threadIdx.x == 0) sh[0] = x;
    }
    __syncthreads();
    float r = sh[0];
    __syncthreads();
    return r;
}

__device__ __forceinline__ float blockReduceSum512(float v, float* sh) {
    #pragma unroll
    for (int off = 16; off > 0; off >>= 1)
        v += __shfl_xor_sync(0xFFFFFFFFu, v, off);
    int lane = threadIdx.x & 31, w = threadIdx.x >> 5;
    if (lane == 0) sh[w] = v;
    __syncthreads();
    if (threadIdx.x < 32) {
        float x = (threadIdx.x < 16) ? sh[threadIdx.x] : 0.f;
        #pragma unroll
        for (int off = 8; off > 0; off >>= 1)
            x += __shfl_xor_sync(0xFFFFFFFFu, x, off);
        if (threadIdx.x == 0) sh[0] = x;
    }
    __syncthreads();
    float r = sh[0];
    __syncthreads();
    return r;
}

// ---------------- K3: fused post-processing (one block per batch) ----------------
// node softmax -> gather + token softmaxes + mix -> 2-hop graph diffusion
__global__ void __launch_bounds__(512)
post_kernel(const int* __restrict__ n2t,
            const float* __restrict__ mask_tok,
            const float* __restrict__ mask_node,
            const float* __restrict__ graph,
            float* __restrict__ d_out) {
    __shared__ float s_attn[NKN];
    __shared__ float s_hop[NKN];
    __shared__ float s_part[512];
    __shared__ float sh[32];

    const int b = blockIdx.x, t = threadIdx.x;   // 512 threads

    // ---- phase 1: node masked-renorm softmax (256 active lanes) ----
    float s = (t < NKN) ? g_scores_node[b * NKN + t] : -INFINITY;
    float mk_n = (t < NKN) ? mask_node[b * NKN + t] : 0.f;
    float m = blockReduceMax512(s, sh);
    float e = (t < NKN) ? __expf(s - m) * mk_n : 0.f;
    float sum = blockReduceSum512(e, sh);
    float a = e / sum;
    if (t < NKN) {
        s_attn[t] = a;
        d_out[BB * HD + BB * TK + b * NKN + t] = a;   // attn_dist_node output
    }
    __syncthreads();

    // ---- phase 2: gather + both token softmaxes + mix ----
    float mk = mask_tok[b * TK + t];
    float sc = g_scores_tok[b * TK + t];
    int nidx = n2t[b * TK + t];
    float g = s_attn[nidx];

    float m1 = blockReduceMax512(sc, sh);
    float e1 = __expf(sc - m1) * mk;
    float s1 = blockReduceSum512(e1, sh);

    float m2 = blockReduceMax512(g, sh);
    float e2 = __expf(g - m2) * mk;
    float s2 = blockReduceSum512(e2, sh);

    float fin = 0.5f * (e1 / s1) + 0.5f * (e2 / s2);
    g_final[b * TK + t] = fin;
    d_out[BB * HD + b * TK + t] = fin;                 // final_attn output
    __syncthreads();

    // ---- phase 3: two-hop graph diffusion ----
    const float* G = graph + (size_t)b * NKN * NKN;
    const int col = t & (NKN - 1);
    const int half = t >> 8;                // 0 or 1: n-range split
    float acc = 0.f;
    #pragma unroll 4
    for (int n = half * 128; n < half * 128 + 128; n++)
        acc = fmaf(s_attn[n], G[n * NKN + col], acc);
    s_part[t] = acc;
    __syncthreads();
    if (t < NKN) s_hop[t] = s_part[t] + s_part[t + NKN];   // one_hop
    __syncthreads();

    float acc2 = 0.f;
    #pragma unroll 4
    for (int n = half * 128; n < half * 128 + 128; n++)
        acc2 = fmaf(s_hop[n], G[n * NKN + col], acc2);
    s_part[t] = acc2;
    __syncthreads();
    if (t < NKN) {
        float two = s_part[t] + s_part[t + NKN];
        float outv = (s_attn[t] + s_hop[t] + two) * 0.33333f;
        d_out[BB * HD + BB * TK + BB * NKN + b * NKN + t] = outv;   // flow_out
    }
}

// ---------------- K4: c_t = final_attn @ enc_tok ----------------
__global__ void ctx_kernel(const float* __restrict__ enc_tok,
                           float* __restrict__ d_out) {
    int b = blockIdx.x, h = threadIdx.x;          // 512 threads, grid (B, 8)
    int t0 = blockIdx.y * 64;
    float acc = 0.f;
    #pragma unroll 8
    for (int t = t0; t < t0 + 64; t++)
        acc = fmaf(g_final[b * TK + t], enc_tok[((size_t)(b * TK + t)) * HD + h], acc);
    atomicAdd(&d_out[b * HD + h], acc);           // c_t output (zeroed in K1)
}

// ---------------- launch ----------------
extern "C" void kernel_launch(void* const* d_in, const int* in_sizes, int n_in,
                              void* d_out, int out_size) {
    const float* s_t_hat   = (const float*)d_in[0];
    const float* enc_tok   = (const float*)d_in[1];
    const float* enc_node  = (const float*)d_in[2];
    const int*   n2t       = (const int*)  d_in[3];
    const float* mask_tok  = (const float*)d_in[4];
    const float* mask_node = (const float*)d_in[5];
    const float* graph     = (const float*)d_in[6];
    const float* flow      = (const float*)d_in[7];
    const float* W_c       = (const float*)d_in[8];
    const float* W_tok     = (const float*)d_in[9];
    const float* W_node    = (const float*)d_in[10];
    const float* W_dec     = (const float*)d_in[11];
    const float* b_dec     = (const float*)d_in[12];
    const float* v_tok     = (const float*)d_in[13];
    const float* v_node    = (const float*)d_in[14];
    float* out = (float*)d_out;

    const int SMEM_BYTES = 3 * (128 * 36 + 32 * 136) * 4;   // 107520
    static bool attr_set = false;
    if (!attr_set) {
        cudaFuncSetAttribute(gemm_score_fused,
                             cudaFuncAttributeMaxDynamicSharedMemorySize, SMEM_BYTES);
        attr_set = true;
    }

    dec_init_kernel<<<BB, HD>>>(s_t_hat, W_dec, b_dec, out);

    gemm_score_fused<<<dim3(HD / 128, 384), 256, SMEM_BYTES>>>(
        enc_tok, enc_node, W_tok, W_node, flow, W_c, v_tok, v_node);

    post_kernel<<<BB, 512>>>(n2t, mask_tok, mask_node, graph, out);

    ctx_kernel<<<dim3(BB, 8), HD>>>(enc_tok, out);
}

// round 7
// speedup vs baseline: 3.6359x; 1.3257x over previous
#include <cuda_runtime.h>
#include <math.h>
#include <stdint.h>

#define HD 512
#define BB 64
#define TK 512
#define NKN 256

// -------- scratch (device globals: no allocations allowed) --------
__device__ float g_dec[BB * HD];
__device__ float g_scores_tok[BB * TK];
__device__ float g_scores_node[BB * NKN];
__device__ float g_final[BB * TK];

// bf16 copies (packed pairs in uint32)
__device__ __align__(16) uint32_t g_bAtok[BB * TK * HD / 2];    // 33.5 MB
__device__ __align__(16) uint32_t g_bAnode[BB * NKN * HD / 2];  // 16.8 MB
__device__ __align__(16) uint32_t g_bWtok[HD * HD / 2];
__device__ __align__(16) uint32_t g_bWnode[HD * HD / 2];

__device__ __forceinline__ float fast_tanh(float x) {
    float y;
    asm("tanh.approx.f32 %0, %1;" : "=f"(y) : "f"(x));
    return y;
}

__device__ __forceinline__ uint32_t bfpack(float lo, float hi) {
    uint32_t r;
    asm("cvt.rn.bf16x2.f32 %0, %1, %2;" : "=r"(r) : "f"(hi), "f"(lo));
    return r;
}

__device__ __forceinline__ void cp16(uint32_t dst, const void* src) {
    asm volatile("cp.async.cg.shared.global [%0], [%1], 16;" :: "r"(dst), "l"(src));
}

// ---------------- K0: fp32 -> bf16 conversion ----------------
#define S0 (BB * TK * HD)     // 16777216
#define S1 (BB * NKN * HD)    // 8388608
#define S2 (HD * HD)          // 262144
__global__ void convert_kernel(const float* __restrict__ A_tok,
                               const float* __restrict__ A_node,
                               const float* __restrict__ Wt,
                               const float* __restrict__ Wn) {
    size_t gid = (size_t)blockIdx.x * blockDim.x + threadIdx.x;
    size_t i8 = gid * 8;
    const float4* s;
    uint4* d;
    if (i8 < S0) {
        s = (const float4*)(A_tok + i8);
        d = (uint4*)g_bAtok + (i8 >> 3);
    } else if (i8 < (size_t)S0 + S1) {
        size_t o = i8 - S0;
        s = (const float4*)(A_node + o);
        d = (uint4*)g_bAnode + (o >> 3);
    } else if (i8 < (size_t)S0 + S1 + S2) {
        size_t o = i8 - S0 - S1;
        s = (const float4*)(Wt + o);
        d = (uint4*)g_bWtok + (o >> 3);
    } else {
        size_t o = i8 - S0 - S1 - S2;
        s = (const float4*)(Wn + o);
        d = (uint4*)g_bWnode + (o >> 3);
    }
    float4 f0 = s[0], f1 = s[1];
    uint4 u;
    u.x = bfpack(f0.x, f0.y);
    u.y = bfpack(f0.z, f0.w);
    u.z = bfpack(f1.x, f1.y);
    u.w = bfpack(f1.z, f1.w);
    d[0] = u;
}

// ---------------- K1: dec_fea + zero scratch/c_t  (grid BB, block 512) --------
__global__ void dec_init_kernel(const float* __restrict__ s_t,
                                const float* __restrict__ Wd,
                                const float* __restrict__ bd,
                                float* __restrict__ d_out) {
    int b = blockIdx.x;
    int h = threadIdx.x;              // blockDim = 512
    g_scores_tok[b * TK + h] = 0.f;
    if (h < NKN) g_scores_node[b * NKN + h] = 0.f;
    d_out[b * HD + h] = 0.f;          // c_t region

    __shared__ float ss[2 * HD];
    for (int k = h; k < 2 * HD; k += HD) ss[k] = s_t[b * 2 * HD + k];
    __syncthreads();
    float acc = bd[h];
    #pragma unroll 8
    for (int k = 0; k < 2 * HD; k++) acc = fmaf(ss[k], Wd[k * HD + h], acc);
    g_dec[b * HD + h] = acc;
}

// ---------------- K2: bf16 mma fused GEMM (token+node) + tanh + v-dot ---------
// grid = (4, 384): by<256 -> token M-tiles, by>=256 -> node M-tiles.
// CTA tile 128x128, BK=64 bf16, 3-stage cp.async ring, ldmatrix fragments.
__global__ void __launch_bounds__(256, 2)
gemm_score_fused(const float* __restrict__ flw,     // [B*NK]
                 const float* __restrict__ Wc,      // [512]
                 const float* __restrict__ v_tok,   // [512]
                 const float* __restrict__ v_node)  // [512]
{
    const int BK = 64, KT = HD / BK;           // 8 k-tiles
    const int STG = 3;
    const int A_BYTES = 128 * 128;             // 128 rows x 128B (64 bf16)
    const int B_BYTES = 64 * 256;              // 64 rows x 256B (128 bf16)
    const int STG_BYTES = A_BYTES + B_BYTES;   // 32768

    extern __shared__ char sm[];
    uint32_t sbase = (uint32_t)__cvta_generic_to_shared(sm);

    const int tid = threadIdx.x;
    const int lane = tid & 31, wid = tid >> 5;
    const int q = lane & 3, rr = lane >> 2;
    const int l15 = lane & 15, lh = lane >> 4;
    const int warp_m = wid & 1;        // 2 row groups of 64
    const int warp_n = wid >> 1;       // 4 col groups of 32
    const bool node = blockIdx.y >= 256;
    const int m0 = node ? (blockIdx.y - 256) * 128 : blockIdx.y * 128;
    const int n0 = blockIdx.x * 128;

    const uint16_t* gA = (const uint16_t*)(node ? g_bAnode : g_bAtok);
    const uint16_t* gW = (const uint16_t*)(node ? g_bWnode : g_bWtok);

    float c[4][4][4];
    #pragma unroll
    for (int mt = 0; mt < 4; mt++)
        #pragma unroll
        for (int nt = 0; nt < 4; nt++)
            #pragma unroll
            for (int k = 0; k < 4; k++) c[mt][nt][k] = 0.f;

    auto load_stage = [&](int kt, int s) {
        uint32_t sb = sbase + s * STG_BYTES;
        // A tile: 128 rows x 8 chunks of 16B
        #pragma unroll
        for (int i = 0; i < 4; i++) {
            int idx = tid + i * 256;
            int r = idx >> 3, cc = idx & 7;
            uint32_t off = r * 128 + cc * 16;
            cp16(sb + (off ^ ((r & 7) << 4)),
                 gA + (size_t)(m0 + r) * HD + kt * BK + cc * 8);
        }
        // B tile: 64 rows x 16 chunks of 16B
        #pragma unroll
        for (int i = 0; i < 4; i++) {
            int idx = tid + i * 256;
            int r = idx >> 4, cc = idx & 15;
            uint32_t off = r * 256 + cc * 16;
            cp16(sb + A_BYTES + (off ^ ((r & 15) << 4)),
                 gW + (size_t)(kt * BK + r) * HD + n0 + cc * 8);
        }
        asm volatile("cp.async.commit_group;" ::: "memory");
    };

    load_stage(0, 0);
    load_stage(1, 1);

    for (int kt = 0; kt < KT; kt++) {
        int s = kt % STG;
        if (kt < KT - 1) asm volatile("cp.async.wait_group 1;" ::: "memory");
        else             asm volatile("cp.async.wait_group 0;" ::: "memory");
        __syncthreads();
        if (kt + 2 < KT) load_stage(kt + 2, (kt + 2) % STG);

        uint32_t sA = sbase + s * STG_BYTES;
        uint32_t sB = sA + A_BYTES;

        #pragma unroll
        for (int kk = 0; kk < 4; kk++) {
            uint32_t bfr[2][4];
            int krow = kk * 16 + l15;
            uint32_t boff = (uint32_t)krow * 256 + warp_n * 64 + lh * 16;
            #pragma unroll
            for (int p = 0; p < 2; p++) {
                uint32_t addr = sB + ((boff + p * 32) ^ ((krow & 15) << 4));
                asm volatile(
                    "ldmatrix.sync.aligned.m8n8.x4.trans.shared.b16 {%0,%1,%2,%3}, [%4];"
                    : "=r"(bfr[p][0]), "=r"(bfr[p][1]),
                      "=r"(bfr[p][2]), "=r"(bfr[p][3]) : "r"(addr));
            }
            #pragma unroll
            for (int mt = 0; mt < 4; mt++) {
                int row = warp_m * 64 + mt * 16 + l15;
                uint32_t addr = sA + ((row * 128 + kk * 32 + lh * 16) ^ ((row & 7) << 4));
                uint32_t a[4];
                asm volatile(
                    "ldmatrix.sync.aligned.m8n8.x4.shared.b16 {%0,%1,%2,%3}, [%4];"
                    : "=r"(a[0]), "=r"(a[1]), "=r"(a[2]), "=r"(a[3]) : "r"(addr));
                #pragma unroll
                for (int nt = 0; nt < 4; nt++) {
                    uint32_t b0 = bfr[nt >> 1][(nt & 1) * 2];
                    uint32_t b1 = bfr[nt >> 1][(nt & 1) * 2 + 1];
                    asm volatile(
                        "mma.sync.aligned.m16n8k16.row.col.f32.bf16.bf16.f32 "
                        "{%0,%1,%2,%3}, {%4,%5,%6,%7}, {%8,%9}, {%0,%1,%2,%3};"
                        : "+f"(c[mt][nt][0]), "+f"(c[mt][nt][1]),
                          "+f"(c[mt][nt][2]), "+f"(c[mt][nt][3])
                        : "r"(a[0]), "r"(a[1]), "r"(a[2]), "r"(a[3]),
                          "r"(b0), "r"(b1));
                }
            }
        }
    }

    // ---- epilogue: tanh + v-dot, quad reduce, atomic partial scores ----
    float* scores = node ? g_scores_node : g_scores_tok;
    const float* v = node ? v_node : v_tok;
    int b = node ? (m0 / NKN) : (m0 / TK);

    float dv[8], vv[8], wc[8];
    #pragma unroll
    for (int nt = 0; nt < 4; nt++) {
        #pragma unroll
        for (int j = 0; j < 2; j++) {
            int n = n0 + warp_n * 32 + nt * 8 + 2 * q + j;
            dv[nt * 2 + j] = g_dec[b * HD + n];
            vv[nt * 2 + j] = v[n];
            wc[nt * 2 + j] = node ? Wc[n] : 0.f;
        }
    }

    #pragma unroll
    for (int mt = 0; mt < 4; mt++) {
        int r = m0 + warp_m * 64 + mt * 16 + rr;
        float fl0 = node ? flw[r] : 0.f;
        float fl1 = node ? flw[r + 8] : 0.f;
        float rs0 = 0.f, rs1 = 0.f;
        #pragma unroll
        for (int nt = 0; nt < 4; nt++) {
            #pragma unroll
            for (int j = 0; j < 2; j++) {
                int e = nt * 2 + j;
                float v0 = fmaf(fl0, wc[e], c[mt][nt][j] + dv[e]);
                float v1 = fmaf(fl1, wc[e], c[mt][nt][2 + j] + dv[e]);
                rs0 += vv[e] * fast_tanh(v0);
                rs1 += vv[e] * fast_tanh(v1);
            }
        }
        rs0 += __shfl_xor_sync(0xFFFFFFFFu, rs0, 1, 4);
        rs0 += __shfl_xor_sync(0xFFFFFFFFu, rs0, 2, 4);
        rs1 += __shfl_xor_sync(0xFFFFFFFFu, rs1, 1, 4);
        rs1 += __shfl_xor_sync(0xFFFFFFFFu, rs1, 2, 4);
        if (q == 0) {
            atomicAdd(&scores[r], rs0);
            atomicAdd(&scores[r + 8], rs1);
        }
    }
}

// ---------------- block reduce helpers (512 threads) ----------------
__device__ __forceinline__ float blockReduceMax512(float v, float* sh) {
    #pragma unroll
    for (int off = 16; off > 0; off >>= 1)
        v = fmaxf(v, __shfl_xor_sync(0xFFFFFFFFu, v, off));
    int lane = threadIdx.x & 31, w = threadIdx.x >> 5;
    if (lane == 0) sh[w] = v;
    __syncthreads();
    if (threadIdx.x < 32) {
        float x = (threadIdx.x < 16) ? sh[threadIdx.x] : -INFINITY;
        #pragma unroll
        for (int off = 8; off > 0; off >>= 1)
            x = fmaxf(x, __shfl_xor_sync(0xFFFFFFFFu, x, off));
        if (threadIdx.x == 0) sh[0] = x;
    }
    __syncthreads();
    float r = sh[0];
    __syncthreads();
    return r;
}

__device__ __forceinline__ float blockReduceSum512(float v, float* sh) {
    #pragma unroll
    for (int off = 16; off > 0; off >>= 1)
        v += __shfl_xor_sync(0xFFFFFFFFu, v, off);
    int lane = threadIdx.x & 31, w = threadIdx.x >> 5;
    if (lane == 0) sh[w] = v;
    __syncthreads();
    if (threadIdx.x < 32) {
        float x = (threadIdx.x < 16) ? sh[threadIdx.x] : 0.f;
        #pragma unroll
        for (int off = 8; off > 0; off >>= 1)
            x += __shfl_xor_sync(0xFFFFFFFFu, x, off);
        if (threadIdx.x == 0) sh[0] = x;
    }
    __syncthreads();
    float r = sh[0];
    __syncthreads();
    return r;
}

// ---------------- K3: fused post-processing (one block per batch) ----------------
__global__ void __launch_bounds__(512)
post_kernel(const int* __restrict__ n2t,
            const float* __restrict__ mask_tok,
            const float* __restrict__ mask_node,
            const float* __restrict__ graph,
            float* __restrict__ d_out) {
    __shared__ float s_attn[NKN];
    __shared__ float s_hop[NKN];
    __shared__ float s_part[512];
    __shared__ float sh[32];

    const int b = blockIdx.x, t = threadIdx.x;   // 512 threads

    // ---- phase 1: node masked-renorm softmax ----
    float s = (t < NKN) ? g_scores_node[b * NKN + t] : -INFINITY;
    float mk_n = (t < NKN) ? mask_node[b * NKN + t] : 0.f;
    float m = blockReduceMax512(s, sh);
    float e = (t < NKN) ? __expf(s - m) * mk_n : 0.f;
    float sum = blockReduceSum512(e, sh);
    float a = e / sum;
    if (t < NKN) {
        s_attn[t] = a;
        d_out[BB * HD + BB * TK + b * NKN + t] = a;   // attn_dist_node output
    }
    __syncthreads();

    // ---- phase 2: gather + both token softmaxes + mix ----
    float mk = mask_tok[b * TK + t];
    float sc = g_scores_tok[b * TK + t];
    int nidx = n2t[b * TK + t];
    float g = s_attn[nidx];

    float m1 = blockReduceMax512(sc, sh);
    float e1 = __expf(sc - m1) * mk;
    float s1 = blockReduceSum512(e1, sh);

    float m2 = blockReduceMax512(g, sh);
    float e2 = __expf(g - m2) * mk;
    float s2 = blockReduceSum512(e2, sh);

    float fin = 0.5f * (e1 / s1) + 0.5f * (e2 / s2);
    g_final[b * TK + t] = fin;
    d_out[BB * HD + b * TK + t] = fin;                 // final_attn output
    __syncthreads();

    // ---- phase 3: two-hop graph diffusion ----
    const float* G = graph + (size_t)b * NKN * NKN;
    const int col = t & (NKN - 1);
    const int half = t >> 8;
    float acc = 0.f;
    #pragma unroll 4
    for (int n = half * 128; n < half * 128 + 128; n++)
        acc = fmaf(s_attn[n], G[n * NKN + col], acc);
    s_part[t] = acc;
    __syncthreads();
    if (t < NKN) s_hop[t] = s_part[t] + s_part[t + NKN];   // one_hop
    __syncthreads();

    float acc2 = 0.f;
    #pragma unroll 4
    for (int n = half * 128; n < half * 128 + 128; n++)
        acc2 = fmaf(s_hop[n], G[n * NKN + col], acc2);
    s_part[t] = acc2;
    __syncthreads();
    if (t < NKN) {
        float two = s_part[t] + s_part[t + NKN];
        float outv = (s_attn[t] + s_hop[t] + two) * 0.33333f;
        d_out[BB * HD + BB * TK + BB * NKN + b * NKN + t] = outv;   // flow_out
    }
}

// ---------------- K4: c_t = final_attn @ enc_tok ----------------
__global__ void ctx_kernel(const float* __restrict__ enc_tok,
                           float* __restrict__ d_out) {
    int b = blockIdx.x, h = threadIdx.x;          // 512 threads, grid (B, 8)
    int t0 = blockIdx.y * 64;
    float acc = 0.f;
    #pragma unroll 8
    for (int t = t0; t < t0 + 64; t++)
        acc = fmaf(g_final[b * TK + t], enc_tok[((size_t)(b * TK + t)) * HD + h], acc);
    atomicAdd(&d_out[b * HD + h], acc);           // c_t output (zeroed in K1)
}

// ---------------- launch ----------------
extern "C" void kernel_launch(void* const* d_in, const int* in_sizes, int n_in,
                              void* d_out, int out_size) {
    const float* s_t_hat   = (const float*)d_in[0];
    const float* enc_tok   = (const float*)d_in[1];
    const float* enc_node  = (const float*)d_in[2];
    const int*   n2t       = (const int*)  d_in[3];
    const float* mask_tok  = (const float*)d_in[4];
    const float* mask_node = (const float*)d_in[5];
    const float* graph     = (const float*)d_in[6];
    const float* flow      = (const float*)d_in[7];
    const float* W_c       = (const float*)d_in[8];
    const float* W_tok     = (const float*)d_in[9];
    const float* W_node    = (const float*)d_in[10];
    const float* W_dec     = (const float*)d_in[11];
    const float* b_dec     = (const float*)d_in[12];
    const float* v_tok     = (const float*)d_in[13];
    const float* v_node    = (const float*)d_in[14];
    float* out = (float*)d_out;

    const int SMEM_BYTES = 3 * 32768;   // 98304
    static bool attr_set = false;
    if (!attr_set) {
        cudaFuncSetAttribute(gemm_score_fused,
                             cudaFuncAttributeMaxDynamicSharedMemorySize, SMEM_BYTES);
        attr_set = true;
    }

    const int CV_THREADS = 256;
    const int CV_BLOCKS = (S0 + S1 + 2 * S2) / 8 / CV_THREADS;   // 12544
    convert_kernel<<<CV_BLOCKS, CV_THREADS>>>(enc_tok, enc_node, W_tok, W_node);

    dec_init_kernel<<<BB, HD>>>(s_t_hat, W_dec, b_dec, out);

    gemm_score_fused<<<dim3(HD / 128, 384), 256, SMEM_BYTES>>>(
        flow, W_c, v_tok, v_node);

    post_kernel<<<BB, 512>>>(n2t, mask_tok, mask_node, graph, out);

    ctx_kernel<<<dim3(BB, 8), HD>>>(enc_tok, out);
}